// round 1
// baseline (speedup 1.0000x reference)
#include <cuda_runtime.h>
#include <stdint.h>

#define B 16
#define N 4096
#define F 128
#define K 1024
#define ROWS_PER_CTA 8

// scratch (no allocations allowed in kernel_launch)
__device__ float g_scores[B * N];
__device__ int   g_topk_idx[B * K];
__device__ float g_topk_val[B * K];

// ---------------------------------------------------------------------------
// Kernel 1: scores[b,n] = dot(node_embed[b,n,:], weight_p)   (one warp per row)
// ---------------------------------------------------------------------------
__global__ void scores_kernel(const float* __restrict__ ne,
                              const float* __restrict__ w) {
    int warp = (blockIdx.x * blockDim.x + threadIdx.x) >> 5;  // row id in [0, B*N)
    int lane = threadIdx.x & 31;
    if (warp >= B * N) return;
    const float4* nrow = reinterpret_cast<const float4*>(ne + (size_t)warp * F);
    const float4* wv   = reinterpret_cast<const float4*>(w);
    float4 a  = nrow[lane];   // 32 lanes x float4 = 128 floats
    float4 b4 = wv[lane];
    float s = a.x * b4.x + a.y * b4.y + a.z * b4.z + a.w * b4.w;
#pragma unroll
    for (int off = 16; off; off >>= 1)
        s += __shfl_xor_sync(0xffffffffu, s, off);
    if (lane == 0) g_scores[warp] = s;
}

// ---------------------------------------------------------------------------
// Kernel 2: per-batch full bitonic sort of 4096 packed keys, keep top-1024.
// key = (monotonic(score) << 12) | (4095 - idx)
//   -> descending sort == jax.lax.top_k order (value desc, tie: lower idx first)
// ---------------------------------------------------------------------------
__device__ __forceinline__ unsigned map_f32(float f) {
    unsigned u = __float_as_uint(f);
    return (u & 0x80000000u) ? ~u : (u | 0x80000000u);  // order-preserving
}

__global__ void topk_kernel() {
    __shared__ unsigned long long s[N];  // 32 KB
    const int b   = blockIdx.x;
    const int tid = threadIdx.x;         // 1024 threads
    const float* sc = g_scores + b * N;

    for (int i = tid; i < N; i += 1024)
        s[i] = (((unsigned long long)map_f32(sc[i])) << 12) |
               (unsigned)(N - 1 - i);
    __syncthreads();

    // bitonic sort, final order descending
    for (int k = 2; k <= N; k <<= 1) {
        for (int j = k >> 1; j > 0; j >>= 1) {
#pragma unroll
            for (int t = 0; t < N / 1024; ++t) {
                int i   = tid + t * 1024;
                int ixj = i ^ j;
                if (ixj > i) {
                    bool desc = ((i & k) == 0);
                    unsigned long long a = s[i], c = s[ixj];
                    bool sw = desc ? (a < c) : (a > c);
                    if (sw) { s[i] = c; s[ixj] = a; }
                }
            }
            __syncthreads();
        }
    }

    // first K entries are the sorted top-k
    unsigned long long key = s[tid];
    int idx = (N - 1) - (int)(key & 0xFFFu);
    g_topk_idx[b * K + tid] = idx;
    g_topk_val[b * K + tid] = sc[idx];
}

// ---------------------------------------------------------------------------
// Kernel 3: pooled_nodes[b,r,:] = node_embed[b, idx, :] * tanh(val)
// one warp per output row, float4 I/O
// ---------------------------------------------------------------------------
__global__ void nodes_kernel(const float* __restrict__ ne,
                             float* __restrict__ out) {
    int warp = (blockIdx.x * blockDim.x + threadIdx.x) >> 5;  // [0, B*K)
    int lane = threadIdx.x & 31;
    if (warp >= B * K) return;
    int b   = warp >> 10;           // warp / K
    int idx = g_topk_idx[warp];
    float g = tanhf(g_topk_val[warp]);
    const float4* src = reinterpret_cast<const float4*>(
        ne + ((size_t)b * N + idx) * F);
    float4* dst = reinterpret_cast<float4*>(out + (size_t)warp * F);
    float4 v = src[lane];
    v.x *= g; v.y *= g; v.z *= g; v.w *= g;
    dst[lane] = v;
}

// ---------------------------------------------------------------------------
// Kernel 4: pooled_adj[b,i,j] = adj[b, idx[i], idx[j]]
// one CTA (256 thr) per 8 output rows; column indices cached in smem
// ---------------------------------------------------------------------------
__global__ void adj_kernel(const float* __restrict__ adj,
                           float* __restrict__ out) {
    __shared__ int cidx[K];
    const int b     = blockIdx.x / (K / ROWS_PER_CTA);
    const int rbase = (blockIdx.x % (K / ROWS_PER_CTA)) * ROWS_PER_CTA;

    for (int j = threadIdx.x; j < K; j += blockDim.x)
        cidx[j] = g_topk_idx[b * K + j];
    __syncthreads();

#pragma unroll
    for (int rr = 0; rr < ROWS_PER_CTA; rr++) {
        int i  = rbase + rr;
        int ri = cidx[i];  // row gather uses the same index list
        const float* row  = adj + ((size_t)b * N + ri) * N;
        float*       orow = out + ((size_t)b * K + i) * K;
#pragma unroll
        for (int j = threadIdx.x; j < K; j += 256)
            orow[j] = __ldg(&row[cidx[j]]);
    }
}

// ---------------------------------------------------------------------------
extern "C" void kernel_launch(void* const* d_in, const int* in_sizes, int n_in,
                              void* d_out, int out_size) {
    const float* ne  = (const float*)d_in[0];  // [B,N,F]
    const float* adj = (const float*)d_in[1];  // [B,N,N]
    const float* w   = (const float*)d_in[2];  // [F]
    float* out       = (float*)d_out;

    // 1) scores: B*N warps, 8 warps/block
    scores_kernel<<<(B * N) / 8, 256>>>(ne, w);
    // 2) per-batch sorted top-k
    topk_kernel<<<B, 1024>>>();
    // 3) pooled_nodes: B*K warps, 8 warps/block
    nodes_kernel<<<(B * K) / 8, 256>>>(ne, out);
    // 4) pooled_adj
    adj_kernel<<<(B * K) / ROWS_PER_CTA, 256>>>(adj,
                                                out + (size_t)B * K * F);
}

// round 3
// speedup vs baseline: 1.3735x; 1.3735x over previous
#include <cuda_runtime.h>
#include <stdint.h>

#define B 16
#define N 4096
#define F 128
#define K 1024
#define ROWS_PER_CTA 8
#define HB 11
#define NB (1 << HB)   // 2048 histogram buckets

typedef unsigned long long u64;
typedef unsigned int u32;

// scratch (no allocations allowed)
__device__ float g_scores[B * N];
__device__ int   g_topk_idx[B * K];
__device__ float g_topk_val[B * K];
__device__ int   g_scol[B * K];   // selected columns sorted ascending
__device__ int   g_spos[B * K];   // original top-k position of that column

// ---------------------------------------------------------------------------
// Kernel 1: scores[b,n] = dot(node_embed[b,n,:], weight_p)   (one warp per row)
// ---------------------------------------------------------------------------
__global__ void scores_kernel(const float* __restrict__ ne,
                              const float* __restrict__ w) {
    int warp = (blockIdx.x * blockDim.x + threadIdx.x) >> 5;
    int lane = threadIdx.x & 31;
    if (warp >= B * N) return;
    const float4* nrow = reinterpret_cast<const float4*>(ne + (size_t)warp * F);
    const float4* wv   = reinterpret_cast<const float4*>(w);
    float4 a  = nrow[lane];
    float4 b4 = wv[lane];
    float s = a.x * b4.x + a.y * b4.y + a.z * b4.z + a.w * b4.w;
#pragma unroll
    for (int off = 16; off; off >>= 1)
        s += __shfl_xor_sync(0xffffffffu, s, off);
    if (lane == 0) g_scores[warp] = s;
}

// ---------------------------------------------------------------------------
// Kernel 2: radix-select + partial bitonic sort.
// key = (monotonic(score) << 12) | (4095 - idx)  -> desc sort == jax top_k order
// ---------------------------------------------------------------------------
__device__ __forceinline__ unsigned map_f32(float f) {
    unsigned u = __float_as_uint(f);
    return (u & 0x80000000u) ? ~u : (u | 0x80000000u);
}

__global__ void __launch_bounds__(1024) topk_kernel() {
    __shared__ u64 cand[4096];       // 32 KB
    __shared__ int hist[NB];         //  8 KB
    __shared__ int wsum[32];
    __shared__ int s_t0, s_cnt;

    const int b    = blockIdx.x;
    const int tid  = threadIdx.x;
    const int lane = tid & 31;
    const int warp = tid >> 5;
    const float* sc = g_scores + b * N;

    hist[tid] = 0;
    hist[tid + 1024] = 0;
    __syncthreads();

    u64 kreg[4];
#pragma unroll
    for (int q = 0; q < 4; q++) {
        int i = tid + q * 1024;
        unsigned m = map_f32(sc[i]);
        kreg[q] = (((u64)m) << 12) | (unsigned)(N - 1 - i);
        atomicAdd(&hist[m >> (32 - HB)], 1);
    }
    __syncthreads();

    // ---- find cutoff bucket t0 = max t such that count(bucket >= t) >= K ----
    // warp w covers buckets [w*64, (w+1)*64)
    {
        int p = hist[2 * tid] + hist[2 * tid + 1];
        int ws = p;
#pragma unroll
        for (int off = 16; off; off >>= 1)
            ws += __shfl_xor_sync(0xffffffffu, ws, off);
        if (lane == 0) wsum[warp] = ws;
    }
    __syncthreads();
    if (warp == 0) {
        int v = wsum[lane];
        int s = v;  // inclusive suffix sum over lanes >= lane
#pragma unroll
        for (int off = 1; off < 32; off <<= 1) {
            int t = __shfl_down_sync(0xffffffffu, s, off);
            if (lane + off < 32) s += t;
        }
        unsigned mm = __ballot_sync(0xffffffffu, s >= K);
        int wstar = 31 - __clz(mm);                 // total = 4096 >= K, mm != 0
        int sW = __shfl_sync(0xffffffffu, s, wstar);
        int vW = __shfl_sync(0xffffffffu, v, wstar);
        int run = sW - vW;                          // count above segment wstar
        int segbase = wstar * 64;
        int t0 = 0;
#pragma unroll
        for (int c = 1; c >= 0; c--) {
            int bkt = segbase + c * 32 + lane;
            int hv = hist[bkt];
            int s2 = hv;
#pragma unroll
            for (int off = 1; off < 32; off <<= 1) {
                int t = __shfl_down_sync(0xffffffffu, s2, off);
                if (lane + off < 32) s2 += t;
            }
            unsigned m2 = __ballot_sync(0xffffffffu, run + s2 >= K);
            if (m2) { t0 = segbase + c * 32 + (31 - __clz(m2)); break; }
            run += __shfl_sync(0xffffffffu, s2, 0);
        }
        if (lane == 0) { s_t0 = t0; s_cnt = 0; }
    }
    __syncthreads();

    // ---- compact candidates (bucket >= t0), count M in [K, ~1.4K] ----
    int t0 = s_t0;
#pragma unroll
    for (int q = 0; q < 4; q++) {
        int bkt = (int)(kreg[q] >> 33);   // bucket = top 11 bits of m = key >> (12+21)
        if (bkt >= t0) {
            int pos = atomicAdd(&s_cnt, 1);
            cand[pos] = kreg[q];
        }
    }
    __syncthreads();
    int M = s_cnt;
    int SL = (M <= 2048) ? 2048 : 4096;   // safety fallback
    for (int i = M + tid; i < SL; i += 1024) cand[i] = 0;
    __syncthreads();

    // ---- bitonic sort descending, SL elements ----
    for (int kk = 2; kk <= SL; kk <<= 1) {
        for (int j = kk >> 1; j > 0; j >>= 1) {
            for (int q = tid; q < (SL >> 1); q += 1024) {
                int i = 2 * q - (q & (j - 1));
                int x = i + j;
                bool desc = ((i & kk) == 0);
                u64 a = cand[i], c = cand[x];
                if (desc ? (a < c) : (a > c)) { cand[i] = c; cand[x] = a; }
            }
            __syncthreads();
        }
    }

    // ---- emit top-K (sorted) ----
    u64 key = cand[tid];
    int idx = (N - 1) - (int)(key & 0xFFFu);
    unsigned m = (unsigned)(key >> 12);
    unsigned u = (m & 0x80000000u) ? (m ^ 0x80000000u) : ~m;
    g_topk_idx[b * K + tid] = idx;
    g_topk_val[b * K + tid] = __uint_as_float(u);

    // ---- column-ascending permutation for the adj gather ----
    u32* cs = (u32*)hist;            // reuse 8 KB
    cs[tid] = ((u32)idx << 10) | (u32)tid;
    __syncthreads();
    for (int kk = 2; kk <= 1024; kk <<= 1) {
        for (int j = kk >> 1; j > 0; j >>= 1) {
            if (tid < 512) {
                int i = 2 * tid - (tid & (j - 1));
                int x = i + j;
                bool asc = ((i & kk) == 0);
                u32 a = cs[i], c = cs[x];
                if (asc ? (a > c) : (a < c)) { cs[i] = c; cs[x] = a; }
            }
            __syncthreads();
        }
    }
    g_scol[b * K + tid] = (int)(cs[tid] >> 10);
    g_spos[b * K + tid] = (int)(cs[tid] & 1023u);
}

// ---------------------------------------------------------------------------
// Kernel 3: pooled_nodes[b,r,:] = node_embed[b, idx, :] * tanh(val)
// ---------------------------------------------------------------------------
__global__ void nodes_kernel(const float* __restrict__ ne,
                             float* __restrict__ out) {
    int warp = (blockIdx.x * blockDim.x + threadIdx.x) >> 5;
    int lane = threadIdx.x & 31;
    if (warp >= B * K) return;
    int b   = warp >> 10;
    int idx = g_topk_idx[warp];
    float g = tanhf(g_topk_val[warp]);
    const float4* src = reinterpret_cast<const float4*>(
        ne + ((size_t)b * N + idx) * F);
    float4* dst = reinterpret_cast<float4*>(out + (size_t)warp * F);
    float4 v = src[lane];
    v.x *= g; v.y *= g; v.z *= g; v.w *= g;
    dst[lane] = v;
}

// ---------------------------------------------------------------------------
// Kernel 4: pooled_adj[b,i,j] = adj[b, row_i, col_j]
// Gather in sorted-column order (DRAM-friendly), restore order via smem
// scatter, store coalesced float4.
// ---------------------------------------------------------------------------
__global__ void __launch_bounds__(256) adj_kernel(const float* __restrict__ adj,
                                                  float* __restrict__ out) {
    __shared__ int   scol[K];
    __shared__ short spos[K];
    __shared__ float buf[K];

    const int b     = blockIdx.x >> 7;                 // 128 CTAs per batch
    const int rbase = (blockIdx.x & 127) * ROWS_PER_CTA;
    const int tid   = threadIdx.x;

#pragma unroll
    for (int q = 0; q < 4; q++) {
        int j = tid + q * 256;
        scol[j] = g_scol[b * K + j];
        spos[j] = (short)g_spos[b * K + j];
    }
    __syncthreads();

    int c0 = scol[4 * tid], c1 = scol[4 * tid + 1];
    int c2 = scol[4 * tid + 2], c3 = scol[4 * tid + 3];
    int p0 = spos[4 * tid], p1 = spos[4 * tid + 1];
    int p2 = spos[4 * tid + 2], p3 = spos[4 * tid + 3];

#pragma unroll
    for (int rr = 0; rr < ROWS_PER_CTA; rr++) {
        int i  = rbase + rr;
        int ri = g_topk_idx[b * K + i];
        const float* row = adj + ((size_t)b * N + ri) * N;
        float v0 = __ldg(row + c0);
        float v1 = __ldg(row + c1);
        float v2 = __ldg(row + c2);
        float v3 = __ldg(row + c3);
        buf[p0] = v0; buf[p1] = v1; buf[p2] = v2; buf[p3] = v3;
        __syncthreads();
        float4 w = *reinterpret_cast<float4*>(&buf[4 * tid]);
        float* orow = out + ((size_t)b * K + i) * K;
        *reinterpret_cast<float4*>(orow + 4 * tid) = w;
        __syncthreads();
    }
}

// ---------------------------------------------------------------------------
extern "C" void kernel_launch(void* const* d_in, const int* in_sizes, int n_in,
                              void* d_out, int out_size) {
    const float* ne  = (const float*)d_in[0];  // [B,N,F]
    const float* adj = (const float*)d_in[1];  // [B,N,N]
    const float* w   = (const float*)d_in[2];  // [F]
    float* out       = (float*)d_out;

    scores_kernel<<<(B * N) / 8, 256>>>(ne, w);
    topk_kernel<<<B, 1024>>>();
    nodes_kernel<<<(B * K) / 8, 256>>>(ne, out);
    adj_kernel<<<(B * K) / ROWS_PER_CTA, 256>>>(adj, out + (size_t)B * K * F);
}

// round 4
// speedup vs baseline: 1.5362x; 1.1184x over previous
#include <cuda_runtime.h>
#include <stdint.h>

#define B 16
#define N 4096
#define F 128
#define K 1024
#define ROWS_PER_CTA 8
#define HB 11
#define NB (1 << HB)   // 2048 histogram buckets

typedef unsigned long long u64;
typedef unsigned int u32;

// scratch (no allocations allowed)
__device__ float g_scores[B * N];
__device__ int   g_topk_idx[B * K];
__device__ float g_topk_val[B * K];
__device__ int   g_scol[B * K];   // selected columns sorted ascending
__device__ int   g_spos[B * K];   // original top-k position of that column

// ---------------------------------------------------------------------------
// Kernel 1: scores[b,n] = dot(node_embed[b,n,:], weight_p)   (one warp per row)
// ---------------------------------------------------------------------------
__global__ void scores_kernel(const float* __restrict__ ne,
                              const float* __restrict__ w) {
    int warp = (blockIdx.x * blockDim.x + threadIdx.x) >> 5;
    int lane = threadIdx.x & 31;
    if (warp >= B * N) return;
    const float4* nrow = reinterpret_cast<const float4*>(ne + (size_t)warp * F);
    const float4* wv   = reinterpret_cast<const float4*>(w);
    float4 a  = nrow[lane];
    float4 b4 = wv[lane];
    float s = a.x * b4.x + a.y * b4.y + a.z * b4.z + a.w * b4.w;
#pragma unroll
    for (int off = 16; off; off >>= 1)
        s += __shfl_xor_sync(0xffffffffu, s, off);
    if (lane == 0) g_scores[warp] = s;
}

// ---------------------------------------------------------------------------
// Kernel 2: radix-select + hybrid register/smem bitonic sort.
// key = (monotonic(score) << 12) | (4095 - idx)  -> desc sort == jax top_k order
// ---------------------------------------------------------------------------
__device__ __forceinline__ unsigned map_f32(float f) {
    unsigned u = __float_as_uint(f);
    return (u & 0x80000000u) ? ~u : (u | 0x80000000u);
}

__device__ __forceinline__ u64 u64max(u64 a, u64 b) { return a > b ? a : b; }
__device__ __forceinline__ u64 u64min(u64 a, u64 b) { return a < b ? a : b; }

// register bitonic stages j = min(kk/2,32) .. 1 on a 64-elem warp tile
// e0 at index i0 = base+lane, e1 at i1 = base+32+lane
__device__ __forceinline__ void reg_stages(u64& e0, u64& e1, int i0, int i1,
                                           int lane, int kk) {
    if (kk >= 64) {  // j = 32: in-thread pair (i0, i1); same direction bit
        bool desc = ((i0 & kk) == 0);
        if (desc ? (e0 < e1) : (e0 > e1)) { u64 t = e0; e0 = e1; e1 = t; }
    }
#pragma unroll
    for (int j = 16; j >= 1; j >>= 1) {
        if (j <= (kk >> 1)) {
            bool d0 = ((i0 & kk) == 0);
            bool d1 = ((i1 & kk) == 0);
            bool up = (lane & j) != 0;
            u64 p0 = __shfl_xor_sync(0xffffffffu, e0, j);
            u64 p1 = __shfl_xor_sync(0xffffffffu, e1, j);
            e0 = (d0 ^ up) ? u64max(e0, p0) : u64min(e0, p0);
            e1 = (d1 ^ up) ? u64max(e1, p1) : u64min(e1, p1);
        }
    }
}

__global__ void __launch_bounds__(1024) topk_kernel() {
    __shared__ u64 cand[4096];       // 32 KB
    __shared__ int hist[NB];         //  8 KB (reused as bitmap later)
    __shared__ int wsum[32];
    __shared__ int s_t0, s_cnt;

    const int b    = blockIdx.x;
    const int tid  = threadIdx.x;
    const int lane = tid & 31;
    const int warp = tid >> 5;
    const float* sc = g_scores + b * N;

    hist[tid] = 0;
    hist[tid + 1024] = 0;
    __syncthreads();

    u64 kreg[4];
#pragma unroll
    for (int q = 0; q < 4; q++) {
        int i = tid + q * 1024;
        unsigned m = map_f32(sc[i]);
        kreg[q] = (((u64)m) << 12) | (unsigned)(N - 1 - i);
        atomicAdd(&hist[m >> (32 - HB)], 1);
    }
    __syncthreads();

    // ---- cutoff bucket t0 = max t such that count(bucket >= t) >= K ----
    {
        int p = hist[2 * tid] + hist[2 * tid + 1];
        int ws = p;
#pragma unroll
        for (int off = 16; off; off >>= 1)
            ws += __shfl_xor_sync(0xffffffffu, ws, off);
        if (lane == 0) wsum[warp] = ws;
    }
    __syncthreads();
    if (warp == 0) {
        int v = wsum[lane];
        int s = v;
#pragma unroll
        for (int off = 1; off < 32; off <<= 1) {
            int t = __shfl_down_sync(0xffffffffu, s, off);
            if (lane + off < 32) s += t;
        }
        unsigned mm = __ballot_sync(0xffffffffu, s >= K);
        int wstar = 31 - __clz(mm);
        int sW = __shfl_sync(0xffffffffu, s, wstar);
        int vW = __shfl_sync(0xffffffffu, v, wstar);
        int run = sW - vW;
        int segbase = wstar * 64;
        int t0 = 0;
#pragma unroll
        for (int c = 1; c >= 0; c--) {
            int bkt = segbase + c * 32 + lane;
            int hv = hist[bkt];
            int s2 = hv;
#pragma unroll
            for (int off = 1; off < 32; off <<= 1) {
                int t = __shfl_down_sync(0xffffffffu, s2, off);
                if (lane + off < 32) s2 += t;
            }
            unsigned m2 = __ballot_sync(0xffffffffu, run + s2 >= K);
            if (m2) { t0 = segbase + c * 32 + (31 - __clz(m2)); break; }
            run += __shfl_sync(0xffffffffu, s2, 0);
        }
        if (lane == 0) { s_t0 = t0; s_cnt = 0; }
    }
    __syncthreads();

    // ---- compact candidates (bucket >= t0) ----
    int t0 = s_t0;
#pragma unroll
    for (int q = 0; q < 4; q++) {
        int bkt = (int)(kreg[q] >> 33);
        if (bkt >= t0) {
            int pos = atomicAdd(&s_cnt, 1);
            cand[pos] = kreg[q];
        }
    }
    __syncthreads();
    int M = s_cnt;

    if (M <= 2048) {
        // pad to 2048 with zeros (real keys are always > 0)
        for (int i = M + tid; i < 2048; i += 1024) cand[i] = 0;
        __syncthreads();

        const int base = warp * 64;
        const int i0 = base + lane, i1 = base + 32 + lane;
        u64 e0, e1;

        // kk = 2..64 entirely in registers
        e0 = cand[i0]; e1 = cand[i1];
#pragma unroll
        for (int kk = 2; kk <= 64; kk <<= 1)
            reg_stages(e0, e1, i0, i1, lane, kk);
        cand[i0] = e0; cand[i1] = e1;
        __syncthreads();

        // kk = 128..2048: smem stages j>=64, then register tail
#pragma unroll
        for (int kk = 128; kk <= 2048; kk <<= 1) {
            for (int j = kk >> 1; j >= 64; j >>= 1) {
                int i = 2 * tid - (tid & (j - 1));
                int x = i + j;
                bool desc = ((i & kk) == 0);
                u64 a = cand[i], c = cand[x];
                if (desc ? (a < c) : (a > c)) { cand[i] = c; cand[x] = a; }
                __syncthreads();
            }
            e0 = cand[i0]; e1 = cand[i1];
            reg_stages(e0, e1, i0, i1, lane, kk);
            cand[i0] = e0; cand[i1] = e1;
            __syncthreads();
        }
    } else {
        // safety fallback: plain full bitonic over all 4096 keys
#pragma unroll
        for (int q = 0; q < 4; q++) cand[tid + q * 1024] = kreg[q];
        __syncthreads();
        for (int kk = 2; kk <= 4096; kk <<= 1) {
            for (int j = kk >> 1; j > 0; j >>= 1) {
                for (int q = tid; q < 2048; q += 1024) {
                    int i = 2 * q - (q & (j - 1));
                    int x = i + j;
                    bool desc = ((i & kk) == 0);
                    u64 a = cand[i], c = cand[x];
                    if (desc ? (a < c) : (a > c)) { cand[i] = c; cand[x] = a; }
                }
                __syncthreads();
            }
        }
    }

    // ---- emit top-K (sorted desc) ----
    u64 key = cand[tid];
    int idx = (N - 1) - (int)(key & 0xFFFu);
    unsigned m = (unsigned)(key >> 12);
    unsigned u = (m & 0x80000000u) ? (m ^ 0x80000000u) : ~m;
    g_topk_idx[b * K + tid] = idx;
    g_topk_val[b * K + tid] = __uint_as_float(u);

    // ---- column-ascending permutation via bitmap counting-rank ----
    u32* bits = (u32*)hist;           // [0..127]  4096-bit presence bitmap
    int* wordpref = hist + 128;       // [128..255] exclusive prefix per word
    if (tid < 128) bits[tid] = 0;
    __syncthreads();
    atomicOr(&bits[idx >> 5], 1u << (idx & 31));
    __syncthreads();
    if (warp == 0) {                  // lane handles words 4l..4l+3
        int s0 = __popc(bits[4 * lane]);
        int s1 = __popc(bits[4 * lane + 1]);
        int s2 = __popc(bits[4 * lane + 2]);
        int s3 = __popc(bits[4 * lane + 3]);
        int tot = s0 + s1 + s2 + s3;
        int ex = tot;
#pragma unroll
        for (int off = 1; off < 32; off <<= 1) {
            int t = __shfl_up_sync(0xffffffffu, ex, off);
            if (lane >= off) ex += t;
        }
        ex -= tot;                    // exclusive scan
        wordpref[4 * lane]     = ex;
        wordpref[4 * lane + 1] = ex + s0;
        wordpref[4 * lane + 2] = ex + s0 + s1;
        wordpref[4 * lane + 3] = ex + s0 + s1 + s2;
    }
    __syncthreads();
    int wrd = idx >> 5, bit = idx & 31;
    int rank = wordpref[wrd] + __popc(bits[wrd] & ((1u << bit) - 1u));
    g_scol[b * K + rank] = idx;
    g_spos[b * K + rank] = tid;
}

// ---------------------------------------------------------------------------
// Kernel 3: pooled_nodes[b,r,:] = node_embed[b, idx, :] * tanh(val)
// ---------------------------------------------------------------------------
__global__ void nodes_kernel(const float* __restrict__ ne,
                             float* __restrict__ out) {
    int warp = (blockIdx.x * blockDim.x + threadIdx.x) >> 5;
    int lane = threadIdx.x & 31;
    if (warp >= B * K) return;
    int b   = warp >> 10;
    int idx = g_topk_idx[warp];
    float g = tanhf(g_topk_val[warp]);
    const float4* src = reinterpret_cast<const float4*>(
        ne + ((size_t)b * N + idx) * F);
    float4* dst = reinterpret_cast<float4*>(out + (size_t)warp * F);
    float4 v = src[lane];
    v.x *= g; v.y *= g; v.z *= g; v.w *= g;
    dst[lane] = v;
}

// ---------------------------------------------------------------------------
// Kernel 4: pooled_adj[b,i,j] = adj[b, row_i, col_j]
// Sorted-column gather, software-pipelined rows, double-buffered smem
// order-restore, coalesced float4 stores. One sync per row.
// ---------------------------------------------------------------------------
__global__ void __launch_bounds__(256) adj_kernel(const float* __restrict__ adj,
                                                  float* __restrict__ out) {
    __shared__ int   scol[K];
    __shared__ short spos[K];
    __shared__ float buf[2][K];
    __shared__ int   ridx[ROWS_PER_CTA];

    const int b     = blockIdx.x >> 7;                 // 128 CTAs per batch
    const int rbase = (blockIdx.x & 127) * ROWS_PER_CTA;
    const int tid   = threadIdx.x;

#pragma unroll
    for (int q = 0; q < 4; q++) {
        int j = tid + q * 256;
        scol[j] = g_scol[b * K + j];
        spos[j] = (short)g_spos[b * K + j];
    }
    if (tid < ROWS_PER_CTA) ridx[tid] = g_topk_idx[b * K + rbase + tid];
    __syncthreads();

    const int c0 = scol[4 * tid],     c1 = scol[4 * tid + 1];
    const int c2 = scol[4 * tid + 2], c3 = scol[4 * tid + 3];
    const int p0 = spos[4 * tid],     p1 = spos[4 * tid + 1];
    const int p2 = spos[4 * tid + 2], p3 = spos[4 * tid + 3];

    const float* row0 = adj + ((size_t)b * N + ridx[0]) * N;
    float a0 = __ldg(row0 + c0), a1 = __ldg(row0 + c1);
    float a2 = __ldg(row0 + c2), a3 = __ldg(row0 + c3);

#pragma unroll
    for (int rr = 0; rr < ROWS_PER_CTA; rr++) {
        float n0, n1, n2, n3;
        if (rr + 1 < ROWS_PER_CTA) {   // issue next row's gathers first
            const float* nr = adj + ((size_t)b * N + ridx[rr + 1]) * N;
            n0 = __ldg(nr + c0); n1 = __ldg(nr + c1);
            n2 = __ldg(nr + c2); n3 = __ldg(nr + c3);
        }
        float* bb = buf[rr & 1];
        bb[p0] = a0; bb[p1] = a1; bb[p2] = a2; bb[p3] = a3;
        __syncthreads();
        float4 w = *reinterpret_cast<float4*>(&bb[4 * tid]);
        float* orow = out + ((size_t)b * K + rbase + rr) * K;
        *reinterpret_cast<float4*>(orow + 4 * tid) = w;
        a0 = n0; a1 = n1; a2 = n2; a3 = n3;
        // buf[rr&1] is re-scattered only at rr+2, after rr+1's barrier: safe.
    }
}

// ---------------------------------------------------------------------------
extern "C" void kernel_launch(void* const* d_in, const int* in_sizes, int n_in,
                              void* d_out, int out_size) {
    const float* ne  = (const float*)d_in[0];  // [B,N,F]
    const float* adj = (const float*)d_in[1];  // [B,N,N]
    const float* w   = (const float*)d_in[2];  // [F]
    float* out       = (float*)d_out;

    scores_kernel<<<(B * N) / 8, 256>>>(ne, w);
    topk_kernel<<<B, 1024>>>();
    nodes_kernel<<<(B * K) / 8, 256>>>(ne, out);
    adj_kernel<<<(B * K) / ROWS_PER_CTA, 256>>>(adj, out + (size_t)B * K * F);
}